// round 15
// baseline (speedup 1.0000x reference)
#include <cuda_runtime.h>
#include <cuda_bf16.h>

#define DINL __device__ __forceinline__
typedef unsigned long long u64;
typedef unsigned int u32;

// ---------------------------------------------------------------------------
// helpers
// ---------------------------------------------------------------------------
DINL u64 ffma2u(u64 a, u64 b, u64 c) {
    u64 d;
    asm("fma.rn.f32x2 %0, %1, %2, %3;" : "=l"(d) : "l"(a), "l"(b), "l"(c));
    return d;
}
DINL u64 add2(u64 a, u64 b) {
    u64 d;
    asm("add.rn.f32x2 %0, %1, %2;" : "=l"(d) : "l"(a), "l"(b));
    return d;
}
DINL u64 pack2(float a, float b) {
    u64 u; asm("mov.b64 %0, {%1, %2};" : "=l"(u) : "f"(a), "f"(b)); return u;
}
DINL float2 unpk(u64 u) {
    float2 v; asm("mov.b64 {%0, %1}, %2;" : "=f"(v.x), "=f"(v.y) : "l"(u)); return v;
}
DINL float tanha(float x) {
    float r; asm("tanh.approx.f32 %0, %1;" : "=f"(r) : "f"(x)); return r;
}
DINL float sigm(float x) { return fmaf(tanha(0.5f * x), 0.5f, 0.5f); }

DINL u32 bfpack(float lo, float hi) {
    __nv_bfloat162 t = __floats2bfloat162_rn(lo, hi);
    return *reinterpret_cast<u32*>(&t);
}

DINL void mma16816(float& c0, float& c1, float& c2, float& c3,
                   u32 a0, u32 a1, u32 a2, u32 a3, u32 b0, u32 b1) {
    asm("mma.sync.aligned.m16n8k16.row.col.f32.bf16.bf16.f32 "
        "{%0,%1,%2,%3}, {%4,%5,%6,%7}, {%8,%9}, {%0,%1,%2,%3};"
        : "+f"(c0), "+f"(c1), "+f"(c2), "+f"(c3)
        : "r"(a0), "r"(a1), "r"(a2), "r"(a3), "r"(b0), "r"(b1));
}

// ---------------------------------------------------------------------------
// Device-global scratch
// ---------------------------------------------------------------------------
__device__ uint4  d_WAb_e1[32 * 8 * 32]; // Whh_e1 bf16 A-fragments [mt][kt][lane]
__device__ float  d_bias_e1[512];
__device__ float4 d_WT4_d1[32 * 512];    // Whh_d1 transposed (fp32, streamed in K4)
__device__ float  d_bias_d1[512];
__device__ float  d_WihT_e2[128 * 256];  // Wih_e2 transposed [k][g]
__device__ float  d_bias_e2[256];
__device__ float  d_h1[4096 * 128];
__device__ float  d_pre2[4096 * 256];    // K3-permuted layout (8-warp scheme)
__device__ float  d_zvec[64];

// ---------------------------------------------------------------------------
// K0: weight packing / bias folding
// ---------------------------------------------------------------------------
__global__ void k0_prep(const float* __restrict__ Whh_e1,
                        const float* __restrict__ bih_e1, const float* __restrict__ bhh_e1,
                        const float* __restrict__ Wih_e2,
                        const float* __restrict__ bih_e2, const float* __restrict__ bhh_e2,
                        const float* __restrict__ Whh_d1,
                        const float* __restrict__ bih_d1, const float* __restrict__ bhh_d1) {
    int stride = gridDim.x * blockDim.x;
    int tid0 = blockIdx.x * blockDim.x + threadIdx.x;
    for (int idx = tid0; idx < 32 * 8 * 32; idx += stride) {
        int lane = idx & 31, kt = (idx >> 5) & 7, mt = idx >> 8;
        int g = lane >> 2, tg = lane & 3;
        int r0 = mt * 16 + g, r1 = r0 + 8;
        int kb = kt * 16;
        uint4 v;
        v.x = bfpack(Whh_e1[r0 * 128 + kb + 2 * tg],     Whh_e1[r0 * 128 + kb + 2 * tg + 1]);
        v.y = bfpack(Whh_e1[r1 * 128 + kb + 2 * tg],     Whh_e1[r1 * 128 + kb + 2 * tg + 1]);
        v.z = bfpack(Whh_e1[r0 * 128 + kb + 2 * tg + 8], Whh_e1[r0 * 128 + kb + 2 * tg + 9]);
        v.w = bfpack(Whh_e1[r1 * 128 + kb + 2 * tg + 8], Whh_e1[r1 * 128 + kb + 2 * tg + 9]);
        d_WAb_e1[idx] = v;
    }
    for (int i = tid0; i < 32 * 512; i += stride) {
        int k4 = i >> 9, g = i & 511;
        const float* r2 = Whh_d1 + g * 128 + 4 * k4;
        d_WT4_d1[i] = make_float4(r2[0], r2[1], r2[2], r2[3]);
    }
    for (int i = tid0; i < 512; i += stride) {
        d_bias_e1[i] = bih_e1[i] + bhh_e1[i];
        d_bias_d1[i] = bih_d1[i] + bhh_d1[i];
    }
    for (int i = tid0; i < 128 * 256; i += stride) {
        int k = i >> 8, g = i & 255;
        d_WihT_e2[i] = Wih_e2[g * 128 + k];
    }
    for (int i = tid0; i < 256; i += stride) d_bias_e2[i] = bih_e2[i] + bhh_e2[i];
}

// ---------------------------------------------------------------------------
// K1: encoder LSTM 1 on tensor cores (bf16 mma.sync m16n8k16). R14-identical.
// ---------------------------------------------------------------------------
#define NB1 32
#define NT1 4
#define XS_STR 34
#define G_STR  36
#define H2_STR 40
#define SM_X   (140 * XS_STR)
#define SM_G   (128 * G_STR)
#define SM_H2  (64 * H2_STR)
#define K1_SMEM ((SM_X + 4 * SM_G + 2 * SM_H2) * 4)

__global__ __launch_bounds__(512, 1) void k1_e1(const float* __restrict__ x,
                                                const float* __restrict__ Wih_e1) {
    extern __shared__ float sm[];
    float* xs = sm;
    float* gi = xs + SM_X;
    float* gf = gi + SM_G;
    float* gg = gf + SM_G;
    float* go = gg + SM_G;
    u32*   h2A = (u32*)(go + SM_G);
    u32*   h2B = h2A + SM_H2;

    const int tid = threadIdx.x;
    const int w = tid >> 5, lane = tid & 31;
    const int g = lane >> 2, tg = lane & 3;
    const int base = blockIdx.x * NB1;

    for (int i = tid; i < NB1 * 140; i += 512) {
        int b = i / 140, t = i - b * 140;
        xs[t * XS_STR + b] = x[(base + b) * 140 + t];
    }
    for (int i = tid; i < 2 * SM_H2; i += 512) h2A[i] = 0u;

    const int mt0 = w, mt1 = w + 16;
    const int r00 = mt0 * 16 + g, r01 = r00 + 8;
    const int r10 = mt1 * 16 + g, r11 = r10 + 8;
    const float wi0 = Wih_e1[r00], wi1 = Wih_e1[r01];
    const float wi2 = Wih_e1[r10], wi3 = Wih_e1[r11];
    const float bb0 = d_bias_e1[r00], bb1 = d_bias_e1[r01];
    const float bb2 = d_bias_e1[r10], bb3 = d_bias_e1[r11];
    const int jb = (w & 7) * 16 + g;
    float* gA = (w < 8) ? gi : gf;
    float* gB = (w < 8) ? gg : go;
    const bool loB_tanh = (w < 8);

    float cr[8];
#pragma unroll
    for (int i = 0; i < 8; ++i) cr[i] = 0.f;
    const int pb_b  = tid & 31;
    const int pb_kp0 = tid >> 5;
    __syncthreads();

    const uint4* __restrict__ WAlo = d_WAb_e1 + mt0 * 8 * 32 + lane;
    const uint4* __restrict__ WAhi = d_WAb_e1 + mt1 * 8 * 32 + lane;

    u32* hcur = h2A;
    u32* hnext = h2B;

    for (int t = 0; t < 140; ++t) {
        float C0[NT1][4], C1[NT1][4];
#pragma unroll
        for (int nt = 0; nt < NT1; ++nt) {
            float2 xp = *(const float2*)&xs[t * XS_STR + nt * 8 + 2 * tg];
            C0[nt][0] = fmaf(wi0, xp.x, bb0); C0[nt][1] = fmaf(wi0, xp.y, bb0);
            C0[nt][2] = fmaf(wi1, xp.x, bb1); C0[nt][3] = fmaf(wi1, xp.y, bb1);
            C1[nt][0] = fmaf(wi2, xp.x, bb2); C1[nt][1] = fmaf(wi2, xp.y, bb2);
            C1[nt][2] = fmaf(wi3, xp.x, bb3); C1[nt][3] = fmaf(wi3, xp.y, bb3);
        }
#pragma unroll
        for (int kt = 0; kt < 8; ++kt) {
            uint4 wlo = WAlo[kt * 32];
            uint4 whi = WAhi[kt * 32];
            const u32* hk0 = hcur + (kt * 8 + tg) * H2_STR;
            const u32* hk1 = hcur + (kt * 8 + tg + 4) * H2_STR;
#pragma unroll
            for (int nt = 0; nt < NT1; ++nt) {
                u32 b0 = hk0[nt * 8 + g];
                u32 b1 = hk1[nt * 8 + g];
                mma16816(C0[nt][0], C0[nt][1], C0[nt][2], C0[nt][3],
                         wlo.x, wlo.y, wlo.z, wlo.w, b0, b1);
                mma16816(C1[nt][0], C1[nt][1], C1[nt][2], C1[nt][3],
                         whi.x, whi.y, whi.z, whi.w, b0, b1);
            }
        }
#pragma unroll
        for (int nt = 0; nt < NT1; ++nt) {
            int bc = nt * 8 + 2 * tg;
            float2 a0 = make_float2(sigm(C0[nt][0]), sigm(C0[nt][1]));
            float2 a1 = make_float2(sigm(C0[nt][2]), sigm(C0[nt][3]));
            float2 b0, b1;
            if (loB_tanh) {
                b0 = make_float2(tanha(C1[nt][0]), tanha(C1[nt][1]));
                b1 = make_float2(tanha(C1[nt][2]), tanha(C1[nt][3]));
            } else {
                b0 = make_float2(sigm(C1[nt][0]), sigm(C1[nt][1]));
                b1 = make_float2(sigm(C1[nt][2]), sigm(C1[nt][3]));
            }
            *(float2*)&gA[jb * G_STR + bc]       = a0;
            *(float2*)&gA[(jb + 8) * G_STR + bc] = a1;
            *(float2*)&gB[jb * G_STR + bc]       = b0;
            *(float2*)&gB[(jb + 8) * G_STR + bc] = b1;
        }
        __syncthreads();
#pragma unroll
        for (int i = 0; i < 4; ++i) {
            int kp = pb_kp0 + 16 * i;
            int j0 = 2 * kp, j1 = j0 + 1;
            float i0 = gi[j0 * G_STR + pb_b], i1 = gi[j1 * G_STR + pb_b];
            float f0 = gf[j0 * G_STR + pb_b], f1 = gf[j1 * G_STR + pb_b];
            float g0 = gg[j0 * G_STR + pb_b], g1 = gg[j1 * G_STR + pb_b];
            float o0 = go[j0 * G_STR + pb_b], o1 = go[j1 * G_STR + pb_b];
            cr[2 * i]     = fmaf(f0, cr[2 * i],     i0 * g0);
            cr[2 * i + 1] = fmaf(f1, cr[2 * i + 1], i1 * g1);
            float h0 = o0 * tanha(cr[2 * i]);
            float h1 = o1 * tanha(cr[2 * i + 1]);
            hnext[kp * H2_STR + pb_b] = bfpack(h0, h1);
            if (t == 139) {
                d_h1[(base + pb_b) * 128 + j0] = h0;
                d_h1[(base + pb_b) * 128 + j1] = h1;
            }
        }
        __syncthreads();
        u32* tmp = hcur; hcur = hnext; hnext = tmp;
    }
}

// ---------------------------------------------------------------------------
// K2: e2 input projection into K3's 8-warp-permuted layout.
// Gate row r: q=r>>6 (i,f,g,o), j=r&63.
// u64 slot p = (j>>3)*16 + (q&1)*8 + (j&7); float pos = q>>1.
// ---------------------------------------------------------------------------
__global__ __launch_bounds__(256, 1) void k2_proj() {
    __shared__ float hsm[32 * 128];
    const int g = threadIdx.x;
    const int t0 = blockIdx.x * 32;
    for (int i = g; i < 32 * 128; i += 256) hsm[i] = d_h1[t0 * 128 + i];
    __syncthreads();
    float acc[32];
#pragma unroll
    for (int r = 0; r < 32; ++r) acc[r] = 0.f;
    for (int k = 0; k < 128; ++k) {
        float w = d_WihT_e2[k * 256 + g];
#pragma unroll
        for (int r = 0; r < 32; ++r) acc[r] = fmaf(hsm[r * 128 + k], w, acc[r]);
    }
    float b = d_bias_e2[g];
    int q = g >> 6, j = g & 63;
    int p = ((j >> 3) << 4) + ((q & 1) << 3) + (j & 7);
    int dst = p * 2 + (q >> 1);
#pragma unroll
    for (int r = 0; r < 32; ++r) d_pre2[(t0 + r) * 256 + dst] = acc[r] + b;
}

// ---------------------------------------------------------------------------
// K3: e2 serial scan. 1 block, 256 threads (8 warps), 4096 steps, H=64.
// Lane: u=l&7 (unit-sub), q2=(l>>3)&1 (i,g vs f,o), kh=l>>4 (k-half).
// Warp w owns units 8w..8w+7. Thread: 2 gate-row HALF dots (16 u64 weights
// each, 32 FFMA2). k-half reduce = shfl_xor(16); gate exchange = shfl_xor(8);
// ONE __syncthreads per step. pre2 u64 slot = w*16 + (l&15), same for both kh.
// ---------------------------------------------------------------------------
__global__ __launch_bounds__(256, 1) void k3_e2(const float* __restrict__ Whh_e2) {
    __shared__ __align__(16) float h_sh[2][64];
    const int tid = threadIdx.x;
    const int w = tid >> 5, l = tid & 31;
    const int u = l & 7;
    const int q2 = (l >> 3) & 1;
    const int kh = l >> 4;
    const int j = 8 * w + u;
    const int r0 = q2 ? (64 + j) : j;          // f : i
    const int r1 = q2 ? (192 + j) : (128 + j); // o : g

    u64 w0[16], w1[16];
    const u64* W2 = (const u64*)Whh_e2;
#pragma unroll
    for (int k = 0; k < 16; ++k) {
        w0[k] = W2[r0 * 32 + 16 * kh + k];
        w1[k] = W2[r1 * 32 + 16 * kh + k];
    }

    if (tid < 64) h_sh[0][tid] = 0.f;
    float c = 0.f;
    const u64* preb = (const u64*)d_pre2;
    const int pslot = w * 16 + (l & 15);     // kh-partners share a slot
    u64 p0 = preb[pslot];
    u64 p1 = preb[128 + pslot];
    __syncthreads();

    for (int t = 0; t < 4096; ++t) {
        u64 p2 = (t < 4094) ? preb[(t + 2) * 128 + pslot] : 0ull;
        const ulonglong2* hp2 =
            (const ulonglong2*)(h_sh[t & 1 ? 1 : 0] + 32 * kh);
        u64 a00 = 0, a01 = 0, a02 = 0, a03 = 0;
        u64 a10 = 0, a11 = 0, a12 = 0, a13 = 0;
#pragma unroll
        for (int i = 0; i < 4; ++i) {
            ulonglong2 ha = hp2[2 * i];
            ulonglong2 hb = hp2[2 * i + 1];
            a00 = ffma2u(w0[4 * i],     ha.x, a00);
            a01 = ffma2u(w0[4 * i + 1], ha.y, a01);
            a02 = ffma2u(w0[4 * i + 2], hb.x, a02);
            a03 = ffma2u(w0[4 * i + 3], hb.y, a03);
            a10 = ffma2u(w1[4 * i],     ha.x, a10);
            a11 = ffma2u(w1[4 * i + 1], ha.y, a11);
            a12 = ffma2u(w1[4 * i + 2], hb.x, a12);
            a13 = ffma2u(w1[4 * i + 3], hb.y, a13);
        }
        a00 = add2(add2(a00, a01), add2(a02, a03));
        a10 = add2(add2(a10, a11), add2(a12, a13));
        float2 v0 = unpk(a00), v1 = unpk(a10);
        float s0 = v0.x + v0.y;
        float s1 = v1.x + v1.y;
        // k-half butterfly (partner has same rows, other k-half)
        s0 += __shfl_xor_sync(0xffffffffu, s0, 16);
        s1 += __shfl_xor_sync(0xffffffffu, s1, 16);
        float2 pc = unpk(p0);
        s0 += pc.x;
        s1 += pc.y;
        float act0 = sigm(s0);                        // i or f
        float act1 = q2 ? sigm(s1) : tanha(s1);       // o or g
        float o0 = __shfl_xor_sync(0xffffffffu, act0, 8);
        float o1 = __shfl_xor_sync(0xffffffffu, act1, 8);
        float iv = q2 ? o0 : act0;
        float fv = q2 ? act0 : o0;
        float gv = q2 ? o1 : act1;
        float ov = q2 ? act1 : o1;
        c = fmaf(fv, c, iv * gv);
        float h = ov * tanha(c);
        if ((l & 24) == 0) h_sh[(t & 1) ^ 1][j] = h;  // q2==0 && kh==0
        __syncthreads();
        p0 = p1; p1 = p2;
    }
    if (tid < 64) d_zvec[tid] = h_sh[0][tid];
}

// ---------------------------------------------------------------------------
// K4: decoder (d1 H=128 + fused d2 H=1). 1 block, 512 threads, 140 steps.
// fp32 weights streamed from d_WT4_d1 (R14-identical).
// ---------------------------------------------------------------------------
__global__ __launch_bounds__(512, 1) void k4_dec(const float* __restrict__ Wih_d1,
                                                 const float* __restrict__ Wih_d2,
                                                 const float* __restrict__ Whh_d2,
                                                 const float* __restrict__ bih_d2,
                                                 const float* __restrict__ bhh_d2,
                                                 float* __restrict__ out) {
    __shared__ float zsh[64];
    __shared__ float h_sh[128];
    __shared__ float gsh[512];
    const int g = threadIdx.x;
    if (g < 64)  zsh[g] = d_zvec[g];
    if (g < 128) h_sh[g] = 0.f;
    __syncthreads();
    float wz = d_bias_d1[g];
#pragma unroll 8
    for (int k = 0; k < 64; ++k) wz = fmaf(Wih_d1[g * 64 + k], zsh[k], wz);
    const bool is_t = (g >= 256 && g < 384);
    float c = 0.f;

    float wd2[16], b2[4], wh[4];
    float c2 = 0.f, h2 = 0.f;
    if (g < 32) {
#pragma unroll
        for (int q = 0; q < 4; ++q) {
#pragma unroll
            for (int m = 0; m < 4; ++m) wd2[q * 4 + m] = Wih_d2[q * 128 + m * 32 + g];
            b2[q] = bih_d2[q] + bhh_d2[q];
            wh[q] = Whh_d2[q];
        }
    }
    const float4* __restrict__ Wp = d_WT4_d1 + g;
    const u64* hs2 = (const u64*)h_sh;

    for (int t = 0; t < 140; ++t) {
        u64 a0 = 0, a1 = 0;
#pragma unroll 8
        for (int k4 = 0; k4 < 32; ++k4) {
            float4 w = Wp[(size_t)k4 * 512];
            a0 = ffma2u(pack2(w.x, w.y), hs2[2 * k4], a0);
            a1 = ffma2u(pack2(w.z, w.w), hs2[2 * k4 + 1], a1);
        }
        a0 = add2(a0, a1);
        float2 v = unpk(a0);
        float xv = v.x + v.y + wz;
        gsh[g] = is_t ? tanha(xv) : sigm(xv);
        __syncthreads();
        if (g < 128) {
            float iv = gsh[g], fv = gsh[128 + g], gv = gsh[256 + g], ov = gsh[384 + g];
            c = fmaf(fv, c, iv * gv);
            h_sh[g] = ov * tanha(c);
        }
        __syncthreads();
        if (g < 32) {
            float p0 = 0.f, p1 = 0.f, p2 = 0.f, p3 = 0.f;
#pragma unroll
            for (int m = 0; m < 4; ++m) {
                float hv = h_sh[m * 32 + g];
                p0 = fmaf(wd2[0 * 4 + m], hv, p0);
                p1 = fmaf(wd2[1 * 4 + m], hv, p1);
                p2 = fmaf(wd2[2 * 4 + m], hv, p2);
                p3 = fmaf(wd2[3 * 4 + m], hv, p3);
            }
#pragma unroll
            for (int off = 16; off > 0; off >>= 1) {
                p0 += __shfl_xor_sync(0xffffffffu, p0, off);
                p1 += __shfl_xor_sync(0xffffffffu, p1, off);
                p2 += __shfl_xor_sync(0xffffffffu, p2, off);
                p3 += __shfl_xor_sync(0xffffffffu, p3, off);
            }
            float iv2 = sigm(p0 + b2[0] + wh[0] * h2);
            float fv2 = sigm(p1 + b2[1] + wh[1] * h2);
            float gv2 = tanha(p2 + b2[2] + wh[2] * h2);
            float ov2 = sigm(p3 + b2[3] + wh[3] * h2);
            c2 = fmaf(fv2, c2, iv2 * gv2);
            h2 = ov2 * tanha(c2);
            if (g == 0) out[t] = h2;
        }
    }
}

// ---------------------------------------------------------------------------
// Launch
// ---------------------------------------------------------------------------
extern "C" void kernel_launch(void* const* d_in, const int* in_sizes, int n_in,
                              void* d_out, int out_size) {
    const float* x      = (const float*)d_in[0];
    const float* Wih_e1 = (const float*)d_in[1];
    const float* Whh_e1 = (const float*)d_in[2];
    const float* bih_e1 = (const float*)d_in[3];
    const float* bhh_e1 = (const float*)d_in[4];
    const float* Wih_e2 = (const float*)d_in[5];
    const float* Whh_e2 = (const float*)d_in[6];
    const float* bih_e2 = (const float*)d_in[7];
    const float* bhh_e2 = (const float*)d_in[8];
    const float* Wih_d1 = (const float*)d_in[9];
    const float* Whh_d1 = (const float*)d_in[10];
    const float* bih_d1 = (const float*)d_in[11];
    const float* bhh_d1 = (const float*)d_in[12];
    const float* Wih_d2 = (const float*)d_in[13];
    const float* Whh_d2 = (const float*)d_in[14];
    const float* bih_d2 = (const float*)d_in[15];
    const float* bhh_d2 = (const float*)d_in[16];
    float* out = (float*)d_out;
    (void)in_sizes; (void)n_in; (void)out_size;

    cudaFuncSetAttribute(k1_e1, cudaFuncAttributeMaxDynamicSharedMemorySize, K1_SMEM);

    k0_prep<<<64, 256>>>(Whh_e1, bih_e1, bhh_e1, Wih_e2, bih_e2, bhh_e2,
                         Whh_d1, bih_d1, bhh_d1);
    k1_e1<<<128, 512, K1_SMEM>>>(x, Wih_e1);
    k2_proj<<<128, 256>>>();
    k3_e2<<<1, 256>>>(Whh_e2);
    k4_dec<<<1, 512>>>(Wih_d1, Wih_d2, Whh_d2, bih_d2, bhh_d2, out);
}

// round 16
// speedup vs baseline: 1.1756x; 1.1756x over previous
#include <cuda_runtime.h>
#include <cuda_bf16.h>

#define DINL __device__ __forceinline__
typedef unsigned long long u64;
typedef unsigned int u32;

// ---------------------------------------------------------------------------
// helpers
// ---------------------------------------------------------------------------
DINL u64 ffma2u(u64 a, u64 b, u64 c) {
    u64 d;
    asm("fma.rn.f32x2 %0, %1, %2, %3;" : "=l"(d) : "l"(a), "l"(b), "l"(c));
    return d;
}
DINL u64 add2(u64 a, u64 b) {
    u64 d;
    asm("add.rn.f32x2 %0, %1, %2;" : "=l"(d) : "l"(a), "l"(b));
    return d;
}
DINL u64 pack2(float a, float b) {
    u64 u; asm("mov.b64 %0, {%1, %2};" : "=l"(u) : "f"(a), "f"(b)); return u;
}
DINL float2 unpk(u64 u) {
    float2 v; asm("mov.b64 {%0, %1}, %2;" : "=f"(v.x), "=f"(v.y) : "l"(u)); return v;
}
DINL float tanha(float x) {
    float r; asm("tanh.approx.f32 %0, %1;" : "=f"(r) : "f"(x)); return r;
}
DINL float sigm(float x) { return fmaf(tanha(0.5f * x), 0.5f, 0.5f); }

DINL u32 bfpack(float lo, float hi) {
    __nv_bfloat162 t = __floats2bfloat162_rn(lo, hi);
    return *reinterpret_cast<u32*>(&t);
}

DINL void mma16816(float& c0, float& c1, float& c2, float& c3,
                   u32 a0, u32 a1, u32 a2, u32 a3, u32 b0, u32 b1) {
    asm("mma.sync.aligned.m16n8k16.row.col.f32.bf16.bf16.f32 "
        "{%0,%1,%2,%3}, {%4,%5,%6,%7}, {%8,%9}, {%0,%1,%2,%3};"
        : "+f"(c0), "+f"(c1), "+f"(c2), "+f"(c3)
        : "r"(a0), "r"(a1), "r"(a2), "r"(a3), "r"(b0), "r"(b1));
}

DINL u32 smem_u32(const void* p) {
    u32 a;
    asm("{ .reg .u64 t; cvta.to.shared.u64 t, %1; cvt.u32.u64 %0, t; }"
        : "=r"(a) : "l"(p));
    return a;
}
DINL u32 mapa_peer(u32 local_addr, u32 peer_rank) {
    u32 r;
    asm("mapa.shared::cluster.u32 %0, %1, %2;" : "=r"(r) : "r"(local_addr), "r"(peer_rank));
    return r;
}
DINL void mbar_wait_parity_cluster(u32 addr, u32 parity) {
    asm volatile(
        "{\n\t.reg .pred P;\n\t"
        "W_%=:\n\t"
        "mbarrier.try_wait.parity.acquire.cluster.shared::cta.b64 P, [%0], %1;\n\t"
        "@!P bra W_%=;\n\t}"
        :: "r"(addr), "r"(parity) : "memory");
}

// ---------------------------------------------------------------------------
// Device-global scratch
// ---------------------------------------------------------------------------
__device__ uint4  d_WAb_e1[32 * 8 * 32]; // Whh_e1 bf16 A-fragments [mt][kt][lane]
__device__ float  d_bias_e1[512];
__device__ float  d_bias_d1[512];
__device__ float  d_WihT_e2[128 * 256];  // Wih_e2 transposed [k][g]
__device__ float  d_bias_e2[256];
__device__ float  d_h1[4096 * 128];
__device__ float  d_pre2[4096 * 256];    // K3-permuted layout (R14 scheme)
__device__ float  d_zvec[64];

// ---------------------------------------------------------------------------
// K0: weight packing / bias folding
// ---------------------------------------------------------------------------
__global__ void k0_prep(const float* __restrict__ Whh_e1,
                        const float* __restrict__ bih_e1, const float* __restrict__ bhh_e1,
                        const float* __restrict__ Wih_e2,
                        const float* __restrict__ bih_e2, const float* __restrict__ bhh_e2,
                        const float* __restrict__ bih_d1, const float* __restrict__ bhh_d1) {
    int stride = gridDim.x * blockDim.x;
    int tid0 = blockIdx.x * blockDim.x + threadIdx.x;
    for (int idx = tid0; idx < 32 * 8 * 32; idx += stride) {
        int lane = idx & 31, kt = (idx >> 5) & 7, mt = idx >> 8;
        int g = lane >> 2, tg = lane & 3;
        int r0 = mt * 16 + g, r1 = r0 + 8;
        int kb = kt * 16;
        uint4 v;
        v.x = bfpack(Whh_e1[r0 * 128 + kb + 2 * tg],     Whh_e1[r0 * 128 + kb + 2 * tg + 1]);
        v.y = bfpack(Whh_e1[r1 * 128 + kb + 2 * tg],     Whh_e1[r1 * 128 + kb + 2 * tg + 1]);
        v.z = bfpack(Whh_e1[r0 * 128 + kb + 2 * tg + 8], Whh_e1[r0 * 128 + kb + 2 * tg + 9]);
        v.w = bfpack(Whh_e1[r1 * 128 + kb + 2 * tg + 8], Whh_e1[r1 * 128 + kb + 2 * tg + 9]);
        d_WAb_e1[idx] = v;
    }
    for (int i = tid0; i < 512; i += stride) {
        d_bias_e1[i] = bih_e1[i] + bhh_e1[i];
        d_bias_d1[i] = bih_d1[i] + bhh_d1[i];
    }
    for (int i = tid0; i < 128 * 256; i += stride) {
        int k = i >> 8, g = i & 255;
        d_WihT_e2[i] = Wih_e2[g * 128 + k];
    }
    for (int i = tid0; i < 256; i += stride) d_bias_e2[i] = bih_e2[i] + bhh_e2[i];
}

// ---------------------------------------------------------------------------
// K1: encoder LSTM 1 on tensor cores (bf16 mma.sync m16n8k16). R14-identical.
// ---------------------------------------------------------------------------
#define NB1 32
#define NT1 4
#define XS_STR 34
#define G_STR  36
#define H2_STR 40
#define SM_X   (140 * XS_STR)
#define SM_G   (128 * G_STR)
#define SM_H2  (64 * H2_STR)
#define K1_SMEM ((SM_X + 4 * SM_G + 2 * SM_H2) * 4)

__global__ __launch_bounds__(512, 1) void k1_e1(const float* __restrict__ x,
                                                const float* __restrict__ Wih_e1) {
    extern __shared__ float sm[];
    float* xs = sm;
    float* gi = xs + SM_X;
    float* gf = gi + SM_G;
    float* gg = gf + SM_G;
    float* go = gg + SM_G;
    u32*   h2A = (u32*)(go + SM_G);
    u32*   h2B = h2A + SM_H2;

    const int tid = threadIdx.x;
    const int w = tid >> 5, lane = tid & 31;
    const int g = lane >> 2, tg = lane & 3;
    const int base = blockIdx.x * NB1;

    for (int i = tid; i < NB1 * 140; i += 512) {
        int b = i / 140, t = i - b * 140;
        xs[t * XS_STR + b] = x[(base + b) * 140 + t];
    }
    for (int i = tid; i < 2 * SM_H2; i += 512) h2A[i] = 0u;

    const int mt0 = w, mt1 = w + 16;
    const int r00 = mt0 * 16 + g, r01 = r00 + 8;
    const int r10 = mt1 * 16 + g, r11 = r10 + 8;
    const float wi0 = Wih_e1[r00], wi1 = Wih_e1[r01];
    const float wi2 = Wih_e1[r10], wi3 = Wih_e1[r11];
    const float bb0 = d_bias_e1[r00], bb1 = d_bias_e1[r01];
    const float bb2 = d_bias_e1[r10], bb3 = d_bias_e1[r11];
    const int jb = (w & 7) * 16 + g;
    float* gA = (w < 8) ? gi : gf;
    float* gB = (w < 8) ? gg : go;
    const bool loB_tanh = (w < 8);

    float cr[8];
#pragma unroll
    for (int i = 0; i < 8; ++i) cr[i] = 0.f;
    const int pb_b  = tid & 31;
    const int pb_kp0 = tid >> 5;
    __syncthreads();

    const uint4* __restrict__ WAlo = d_WAb_e1 + mt0 * 8 * 32 + lane;
    const uint4* __restrict__ WAhi = d_WAb_e1 + mt1 * 8 * 32 + lane;

    u32* hcur = h2A;
    u32* hnext = h2B;

    for (int t = 0; t < 140; ++t) {
        float C0[NT1][4], C1[NT1][4];
#pragma unroll
        for (int nt = 0; nt < NT1; ++nt) {
            float2 xp = *(const float2*)&xs[t * XS_STR + nt * 8 + 2 * tg];
            C0[nt][0] = fmaf(wi0, xp.x, bb0); C0[nt][1] = fmaf(wi0, xp.y, bb0);
            C0[nt][2] = fmaf(wi1, xp.x, bb1); C0[nt][3] = fmaf(wi1, xp.y, bb1);
            C1[nt][0] = fmaf(wi2, xp.x, bb2); C1[nt][1] = fmaf(wi2, xp.y, bb2);
            C1[nt][2] = fmaf(wi3, xp.x, bb3); C1[nt][3] = fmaf(wi3, xp.y, bb3);
        }
#pragma unroll
        for (int kt = 0; kt < 8; ++kt) {
            uint4 wlo = WAlo[kt * 32];
            uint4 whi = WAhi[kt * 32];
            const u32* hk0 = hcur + (kt * 8 + tg) * H2_STR;
            const u32* hk1 = hcur + (kt * 8 + tg + 4) * H2_STR;
#pragma unroll
            for (int nt = 0; nt < NT1; ++nt) {
                u32 b0 = hk0[nt * 8 + g];
                u32 b1 = hk1[nt * 8 + g];
                mma16816(C0[nt][0], C0[nt][1], C0[nt][2], C0[nt][3],
                         wlo.x, wlo.y, wlo.z, wlo.w, b0, b1);
                mma16816(C1[nt][0], C1[nt][1], C1[nt][2], C1[nt][3],
                         whi.x, whi.y, whi.z, whi.w, b0, b1);
            }
        }
#pragma unroll
        for (int nt = 0; nt < NT1; ++nt) {
            int bc = nt * 8 + 2 * tg;
            float2 a0 = make_float2(sigm(C0[nt][0]), sigm(C0[nt][1]));
            float2 a1 = make_float2(sigm(C0[nt][2]), sigm(C0[nt][3]));
            float2 b0, b1;
            if (loB_tanh) {
                b0 = make_float2(tanha(C1[nt][0]), tanha(C1[nt][1]));
                b1 = make_float2(tanha(C1[nt][2]), tanha(C1[nt][3]));
            } else {
                b0 = make_float2(sigm(C1[nt][0]), sigm(C1[nt][1]));
                b1 = make_float2(sigm(C1[nt][2]), sigm(C1[nt][3]));
            }
            *(float2*)&gA[jb * G_STR + bc]       = a0;
            *(float2*)&gA[(jb + 8) * G_STR + bc] = a1;
            *(float2*)&gB[jb * G_STR + bc]       = b0;
            *(float2*)&gB[(jb + 8) * G_STR + bc] = b1;
        }
        __syncthreads();
#pragma unroll
        for (int i = 0; i < 4; ++i) {
            int kp = pb_kp0 + 16 * i;
            int j0 = 2 * kp, j1 = j0 + 1;
            float i0 = gi[j0 * G_STR + pb_b], i1 = gi[j1 * G_STR + pb_b];
            float f0 = gf[j0 * G_STR + pb_b], f1 = gf[j1 * G_STR + pb_b];
            float g0 = gg[j0 * G_STR + pb_b], g1 = gg[j1 * G_STR + pb_b];
            float o0 = go[j0 * G_STR + pb_b], o1 = go[j1 * G_STR + pb_b];
            cr[2 * i]     = fmaf(f0, cr[2 * i],     i0 * g0);
            cr[2 * i + 1] = fmaf(f1, cr[2 * i + 1], i1 * g1);
            float h0 = o0 * tanha(cr[2 * i]);
            float h1 = o1 * tanha(cr[2 * i + 1]);
            hnext[kp * H2_STR + pb_b] = bfpack(h0, h1);
            if (t == 139) {
                d_h1[(base + pb_b) * 128 + j0] = h0;
                d_h1[(base + pb_b) * 128 + j1] = h1;
            }
        }
        __syncthreads();
        u32* tmp = hcur; hcur = hnext; hnext = tmp;
    }
}

// ---------------------------------------------------------------------------
// K2: e2 input projection into K3-permuted layout (R14-identical)
// ---------------------------------------------------------------------------
__global__ __launch_bounds__(256, 1) void k2_proj() {
    __shared__ float hsm[32 * 128];
    const int g = threadIdx.x;
    const int t0 = blockIdx.x * 32;
    for (int i = g; i < 32 * 128; i += 256) hsm[i] = d_h1[t0 * 128 + i];
    __syncthreads();
    float acc[32];
#pragma unroll
    for (int r = 0; r < 32; ++r) acc[r] = 0.f;
    for (int k = 0; k < 128; ++k) {
        float w = d_WihT_e2[k * 256 + g];
#pragma unroll
        for (int r = 0; r < 32; ++r) acc[r] = fmaf(hsm[r * 128 + k], w, acc[r]);
    }
    float b = d_bias_e2[g];
    int q = g >> 6, j = g & 63;
    int q2 = q & 1, slot = q >> 1;
    int tid2 = (j >> 4) * 32 + (q2 << 4) + (j & 15);
    int dst = tid2 * 2 + slot;
#pragma unroll
    for (int r = 0; r < 32; ++r) d_pre2[(t0 + r) * 256 + dst] = acc[r] + b;
}

// ---------------------------------------------------------------------------
// K3: e2 serial scan. 1 block, 128 threads, 4096 steps, H=64. R14-identical.
// ---------------------------------------------------------------------------
__global__ __launch_bounds__(128, 1) void k3_e2(const float* __restrict__ Whh_e2) {
    __shared__ __align__(16) float h_sh[2][64];
    const int tid = threadIdx.x;
    const int w = tid >> 5, l = tid & 31;
    const int j = w * 16 + (l & 15);
    const int q2 = l >> 4;
    const int r0 = q2 ? (64 + j) : j;
    const int r1 = q2 ? (192 + j) : (128 + j);

    u64 w0[32], w1[32];
    const u64* W2 = (const u64*)Whh_e2;
#pragma unroll
    for (int k = 0; k < 32; ++k) { w0[k] = W2[r0 * 32 + k]; w1[k] = W2[r1 * 32 + k]; }

    if (tid < 64) h_sh[0][tid] = 0.f;
    float c = 0.f;
    const u64* preb = (const u64*)d_pre2;
    u64 p0 = preb[tid];
    u64 p1 = preb[128 + tid];
    __syncthreads();

    for (int t = 0; t < 4096; ++t) {
        u64 p2 = (t < 4094) ? preb[(t + 2) * 128 + tid] : 0ull;
        const ulonglong2* hp2 = (const ulonglong2*)h_sh[t & 1 ? 1 : 0];
        float2 pc = unpk(p0);
        u64 a00 = pack2(pc.x, 0.f), a01 = 0, a02 = 0, a03 = 0;
        u64 a10 = pack2(pc.y, 0.f), a11 = 0, a12 = 0, a13 = 0;
#pragma unroll
        for (int k = 0; k < 16; k += 2) {
            ulonglong2 ha = hp2[k];
            ulonglong2 hb = hp2[k + 1];
            a00 = ffma2u(w0[2 * k],     ha.x, a00);
            a01 = ffma2u(w0[2 * k + 1], ha.y, a01);
            a02 = ffma2u(w0[2 * k + 2], hb.x, a02);
            a03 = ffma2u(w0[2 * k + 3], hb.y, a03);
            a10 = ffma2u(w1[2 * k],     ha.x, a10);
            a11 = ffma2u(w1[2 * k + 1], ha.y, a11);
            a12 = ffma2u(w1[2 * k + 2], hb.x, a12);
            a13 = ffma2u(w1[2 * k + 3], hb.y, a13);
        }
        a00 = add2(add2(a00, a01), add2(a02, a03));
        a10 = add2(add2(a10, a11), add2(a12, a13));
        float2 v0 = unpk(a00), v1 = unpk(a10);
        float s0 = v0.x + v0.y;
        float s1 = v1.x + v1.y;
        float act0 = sigm(s0);
        float act1 = q2 ? sigm(s1) : tanha(s1);
        float o0 = __shfl_xor_sync(0xffffffffu, act0, 16);
        float o1 = __shfl_xor_sync(0xffffffffu, act1, 16);
        float iv = q2 ? o0 : act0;
        float fv = q2 ? act0 : o0;
        float gv = q2 ? o1 : act1;
        float ov = q2 ? act1 : o1;
        c = fmaf(fv, c, iv * gv);
        float h = ov * tanha(c);
        if (q2 == 0) h_sh[(t & 1) ^ 1][j] = h;
        __syncthreads();
        p0 = p1; p1 = p2;
    }
    if (tid < 64) d_zvec[tid] = h_sh[0][tid];
}

// ---------------------------------------------------------------------------
// K4: decoder d1 split across a 2-CTA CLUSTER, weights in registers; fused d2.
// CTA rank owns units [64r, 64r+64): 256 gate rows, 128 KB weights preloaded
// into regs (64/thread). Thread: rr=tid>>1 (row), kh=tid&1 (k-half);
// unit jj=tid>>3, q=(tid>>1)&3 -> unit = 8 contiguous lanes.
// Per step: 32 FFMA2 dot + shfl_xor(1) k-reduce + shfl_xor(4)+shfl_xor(2)
// gate combine (c,h at q==1). h-half exchanged via st.shared::cluster +
// mbarrier arrive/wait (32 arrivals). d2 on rank0 warp0 after the wait.
// ---------------------------------------------------------------------------
__global__ __launch_bounds__(512, 1) __cluster_dims__(2, 1, 1)
void k4_dec(const float* __restrict__ Wih_d1,
            const float* __restrict__ Whh_d1,
            const float* __restrict__ Wih_d2,
            const float* __restrict__ Whh_d2,
            const float* __restrict__ bih_d2,
            const float* __restrict__ bhh_d2,
            float* __restrict__ out) {
    __shared__ __align__(16) float hbuf[2][128];
    __shared__ __align__(8) u64 mbar[1];
    __shared__ float zsh[64];

    const int tid = threadIdx.x;
    u32 rank;
    asm("mov.u32 %0, %%cluster_ctarank;" : "=r"(rank));
    const u32 peer = rank ^ 1u;

    const u32 mbar_a = smem_u32(mbar);
    const u32 hbuf_a = smem_u32(&hbuf[0][0]);

    if (tid == 0) {
        asm volatile("mbarrier.init.shared.b64 [%0], %1;" :: "r"(mbar_a), "r"(32u) : "memory");
    }
    if (tid < 64) zsh[tid] = d_zvec[tid];
    if (tid < 128) hbuf[0][tid] = 0.f;
    __syncthreads();
    asm volatile("barrier.cluster.arrive.aligned;" ::: "memory");
    asm volatile("barrier.cluster.wait.aligned;" ::: "memory");

    // thread roles
    const int kh = tid & 1;
    const int q  = (tid >> 1) & 3;
    const int jj = tid >> 3;                  // 0..63 local unit
    const int J  = 64 * (int)rank + jj;       // global unit
    const int row = q * 128 + J;              // gate row

    // weights (k-half) into registers: floats [64kh, 64kh+64)
    float4 Wreg[16];
    {
        const float4* wp = (const float4*)(Whh_d1 + (size_t)row * 128 + kh * 64);
#pragma unroll
        for (int i = 0; i < 16; ++i) Wreg[i] = wp[i];
    }
    // constant input projection (split across kh)
    float wz = (kh == 0) ? d_bias_d1[row] : 0.f;
#pragma unroll 8
    for (int k = 0; k < 32; ++k)
        wz = fmaf(Wih_d1[row * 64 + kh * 32 + k], zsh[kh * 32 + k], wz);

    // d2 state (rank 0, warp 0)
    float wd2[16], b2[4], wh[4];
    float c2s = 0.f, h2s = 0.f;
    if (rank == 0 && tid < 32) {
#pragma unroll
        for (int qq = 0; qq < 4; ++qq) {
#pragma unroll
            for (int m = 0; m < 4; ++m) wd2[qq * 4 + m] = Wih_d2[qq * 128 + m * 32 + tid];
            b2[qq] = bih_d2[qq] + bhh_d2[qq];
            wh[qq] = Whh_d2[qq];
        }
    }

    float c = 0.f;
    u32 ph = 0;

    for (int t = 0; t < 140; ++t) {
        const int rb = t & 1;
        const int wb = rb ^ 1;
        const ulonglong2* hp = (const ulonglong2*)(hbuf[rb]) + 16 * kh;
        u64 a0 = pack2(wz, 0.f), a1 = 0, a2 = 0, a3 = 0;
#pragma unroll
        for (int i = 0; i < 4; ++i) {
            ulonglong2 hA = hp[4 * i],     hB = hp[4 * i + 1];
            ulonglong2 hC = hp[4 * i + 2], hD = hp[4 * i + 3];
            a0 = ffma2u(pack2(Wreg[4 * i].x,     Wreg[4 * i].y),     hA.x, a0);
            a1 = ffma2u(pack2(Wreg[4 * i].z,     Wreg[4 * i].w),     hA.y, a1);
            a2 = ffma2u(pack2(Wreg[4 * i + 1].x, Wreg[4 * i + 1].y), hB.x, a2);
            a3 = ffma2u(pack2(Wreg[4 * i + 1].z, Wreg[4 * i + 1].w), hB.y, a3);
            a0 = ffma2u(pack2(Wreg[4 * i + 2].x, Wreg[4 * i + 2].y), hC.x, a0);
            a1 = ffma2u(pack2(Wreg[4 * i + 2].z, Wreg[4 * i + 2].w), hC.y, a1);
            a2 = ffma2u(pack2(Wreg[4 * i + 3].x, Wreg[4 * i + 3].y), hD.x, a2);
            a3 = ffma2u(pack2(Wreg[4 * i + 3].z, Wreg[4 * i + 3].w), hD.y, a3);
        }
        a0 = add2(add2(a0, a1), add2(a2, a3));
        float2 v = unpk(a0);
        float s = v.x + v.y;
        s += __shfl_xor_sync(0xffffffffu, s, 1);          // k-half reduce
        float act = (q == 2) ? tanha(s) : sigm(s);         // i,f,o: sigm; g: tanh
        float r4 = __shfl_xor_sync(0xffffffffu, act, 4);   // q0<-g, q1<-o
        float ig = act * r4;                                // valid at q0
        float r2 = __shfl_xor_sync(0xffffffffu, ig, 2);     // q1 <- ig
        float hval = 0.f;
        if (q == 1) {
            c = fmaf(act, c, r2);                           // c = f*c + i*g
            hval = r4 * tanha(c);                           // h = o*tanh(c)
            if (kh == 0) hbuf[wb][J] = hval;
        }
        __syncthreads();
        // push own 64-float h-half (32 u64) to peer + arrive on peer's bar
        if (tid >= 32 && tid < 64) {
            int i = tid - 32;
            int idx = 32 * (int)rank + i;                   // u64 index in hbuf[wb]
            u64 val = ((const u64*)hbuf[wb])[idx];
            u32 dsta = mapa_peer(hbuf_a + (u32)(wb * 128 + 0) * 4 + (u32)idx * 8, peer);
            asm volatile("st.shared::cluster.b64 [%0], %1;" :: "r"(dsta), "l"(val) : "memory");
            u32 pb = mapa_peer(mbar_a, peer);
            asm volatile("mbarrier.arrive.release.cluster.shared::cluster.b64 _, [%0];"
                         :: "r"(pb) : "memory");
        }
        mbar_wait_parity_cluster(mbar_a, ph);
        ph ^= 1u;
        // d2 (rank 0, warp 0) on full h of this step
        if (rank == 0 && tid < 32) {
            float p0 = 0.f, p1 = 0.f, p2 = 0.f, p3 = 0.f;
#pragma unroll
            for (int m = 0; m < 4; ++m) {
                float hv = hbuf[wb][m * 32 + tid];
                p0 = fmaf(wd2[0 * 4 + m], hv, p0);
                p1 = fmaf(wd2[1 * 4 + m], hv, p1);
                p2 = fmaf(wd2[2 * 4 + m], hv, p2);
                p3 = fmaf(wd2[3 * 4 + m], hv, p3);
            }
#pragma unroll
            for (int off = 16; off > 0; off >>= 1) {
                p0 += __shfl_xor_sync(0xffffffffu, p0, off);
                p1 += __shfl_xor_sync(0xffffffffu, p1, off);
                p2 += __shfl_xor_sync(0xffffffffu, p2, off);
                p3 += __shfl_xor_sync(0xffffffffu, p3, off);
            }
            float iv2 = sigm(p0 + b2[0] + wh[0] * h2s);
            float fv2 = sigm(p1 + b2[1] + wh[1] * h2s);
            float gv2 = tanha(p2 + b2[2] + wh[2] * h2s);
            float ov2 = sigm(p3 + b2[3] + wh[3] * h2s);
            c2s = fmaf(fv2, c2s, iv2 * gv2);
            h2s = ov2 * tanha(c2s);
            if (tid == 0) out[t] = h2s;
        }
    }
    asm volatile("barrier.cluster.arrive.aligned;" ::: "memory");
    asm volatile("barrier.cluster.wait.aligned;" ::: "memory");
}

// ---------------------------------------------------------------------------
// Launch
// ---------------------------------------------------------------------------
extern "C" void kernel_launch(void* const* d_in, const int* in_sizes, int n_in,
                              void* d_out, int out_size) {
    const float* x      = (const float*)d_in[0];
    const float* Wih_e1 = (const float*)d_in[1];
    const float* Whh_e1 = (const float*)d_in[2];
    const float* bih_e1 = (const float*)d_in[3];
    const float* bhh_e1 = (const float*)d_in[4];
    const float* Wih_e2 = (const float*)d_in[5];
    const float* Whh_e2 = (const float*)d_in[6];
    const float* bih_e2 = (const float*)d_in[7];
    const float* bhh_e2 = (const float*)d_in[8];
    const float* Wih_d1 = (const float*)d_in[9];
    const float* Whh_d1 = (const float*)d_in[10];
    const float* bih_d1 = (const float*)d_in[11];
    const float* bhh_d1 = (const float*)d_in[12];
    const float* Wih_d2 = (const float*)d_in[13];
    const float* Whh_d2 = (const float*)d_in[14];
    const float* bih_d2 = (const float*)d_in[15];
    const float* bhh_d2 = (const float*)d_in[16];
    float* out = (float*)d_out;
    (void)in_sizes; (void)n_in; (void)out_size;

    cudaFuncSetAttribute(k1_e1, cudaFuncAttributeMaxDynamicSharedMemorySize, K1_SMEM);

    k0_prep<<<64, 256>>>(Whh_e1, bih_e1, bhh_e1, Wih_e2, bih_e2, bhh_e2,
                         bih_d1, bhh_d1);
    k1_e1<<<128, 512, K1_SMEM>>>(x, Wih_e1);
    k2_proj<<<128, 256>>>();
    k3_e2<<<1, 128>>>(Whh_e2);
    k4_dec<<<2, 512>>>(Wih_d1, Whh_d1, Wih_d2, Whh_d2, bih_d2, bhh_d2, out);
}

// round 17
// speedup vs baseline: 1.2558x; 1.0682x over previous
#include <cuda_runtime.h>
#include <cuda_bf16.h>

#define DINL __device__ __forceinline__
typedef unsigned long long u64;
typedef unsigned int u32;

// ---------------------------------------------------------------------------
// helpers
// ---------------------------------------------------------------------------
DINL u64 ffma2u(u64 a, u64 b, u64 c) {
    u64 d;
    asm("fma.rn.f32x2 %0, %1, %2, %3;" : "=l"(d) : "l"(a), "l"(b), "l"(c));
    return d;
}
DINL u64 add2(u64 a, u64 b) {
    u64 d;
    asm("add.rn.f32x2 %0, %1, %2;" : "=l"(d) : "l"(a), "l"(b));
    return d;
}
DINL u64 pack2(float a, float b) {
    u64 u; asm("mov.b64 %0, {%1, %2};" : "=l"(u) : "f"(a), "f"(b)); return u;
}
DINL float2 unpk(u64 u) {
    float2 v; asm("mov.b64 {%0, %1}, %2;" : "=f"(v.x), "=f"(v.y) : "l"(u)); return v;
}
DINL float tanha(float x) {
    float r; asm("tanh.approx.f32 %0, %1;" : "=f"(r) : "f"(x)); return r;
}
DINL float sigm(float x) { return fmaf(tanha(0.5f * x), 0.5f, 0.5f); }

DINL u32 bfpack(float lo, float hi) {
    __nv_bfloat162 t = __floats2bfloat162_rn(lo, hi);
    return *reinterpret_cast<u32*>(&t);
}

DINL void mma16816(float& c0, float& c1, float& c2, float& c3,
                   u32 a0, u32 a1, u32 a2, u32 a3, u32 b0, u32 b1) {
    asm("mma.sync.aligned.m16n8k16.row.col.f32.bf16.bf16.f32 "
        "{%0,%1,%2,%3}, {%4,%5,%6,%7}, {%8,%9}, {%0,%1,%2,%3};"
        : "+f"(c0), "+f"(c1), "+f"(c2), "+f"(c3)
        : "r"(a0), "r"(a1), "r"(a2), "r"(a3), "r"(b0), "r"(b1));
}

DINL u32 smem_u32(const void* p) {
    u32 a;
    asm("{ .reg .u64 t; cvta.to.shared.u64 t, %1; cvt.u32.u64 %0, t; }"
        : "=r"(a) : "l"(p));
    return a;
}
DINL u32 mapa_peer(u32 local_addr, u32 peer_rank) {
    u32 r;
    asm("mapa.shared::cluster.u32 %0, %1, %2;" : "=r"(r) : "r"(local_addr), "r"(peer_rank));
    return r;
}
DINL void mbar_wait_parity_cluster(u32 addr, u32 parity) {
    asm volatile(
        "{\n\t.reg .pred P;\n\t"
        "W_%=:\n\t"
        "mbarrier.try_wait.parity.acquire.cluster.shared::cta.b64 P, [%0], %1;\n\t"
        "@!P bra W_%=;\n\t}"
        :: "r"(addr), "r"(parity) : "memory");
}
DINL u32 ld_acq(const u32* p) {
    u32 v;
    asm volatile("ld.global.acquire.gpu.b32 %0, [%1];" : "=r"(v) : "l"(p) : "memory");
    return v;
}
DINL void st_rel(u32* p, u32 v) {
    asm volatile("st.global.release.gpu.b32 [%0], %1;" :: "l"(p), "r"(v) : "memory");
}

// k-slot permutation: slot-pair m holds units (16*(m>>3)+(m&7), +8)
DINL int uslot(int s) {
    int m = s >> 1;
    return 16 * (m >> 3) + (m & 7) + 8 * (s & 1);
}

// ---------------------------------------------------------------------------
// Device-global scratch
// ---------------------------------------------------------------------------
__device__ uint4  d_WAb_e1[32 * 8 * 32]; // Whh_e1 bf16 A-frags, uslot-permuted k
__device__ float  d_bias_e1[512];
__device__ float  d_bias_d1[512];
__device__ float  d_WihT_e2[128 * 256];  // Wih_e2 transposed [k][g]
__device__ float  d_bias_e2[256];
__device__ float  d_pre2[4096 * 256];    // K3-permuted layout
__device__ float  d_zvec[64];
__device__ u32    d_flags[256];          // pre2 chunk-ready flags (16 t each)

// ---------------------------------------------------------------------------
// K0: weight packing / bias folding
// ---------------------------------------------------------------------------
__global__ void k0_prep(const float* __restrict__ Whh_e1,
                        const float* __restrict__ bih_e1, const float* __restrict__ bhh_e1,
                        const float* __restrict__ Wih_e2,
                        const float* __restrict__ bih_e2, const float* __restrict__ bhh_e2,
                        const float* __restrict__ bih_d1, const float* __restrict__ bhh_d1) {
    int stride = gridDim.x * blockDim.x;
    int tid0 = blockIdx.x * blockDim.x + threadIdx.x;
    // Whh_e1 -> bf16 m16n8k16 A fragments with uslot k-permutation
    for (int idx = tid0; idx < 32 * 8 * 32; idx += stride) {
        int lane = idx & 31, kt = (idx >> 5) & 7, mt = idx >> 8;
        int g = lane >> 2, tg = lane & 3;
        int r0 = mt * 16 + g, r1 = r0 + 8;
        int s0 = kt * 16 + 2 * tg;
        int s2 = s0 + 8;
        uint4 v;
        v.x = bfpack(Whh_e1[r0 * 128 + uslot(s0)], Whh_e1[r0 * 128 + uslot(s0 + 1)]);
        v.y = bfpack(Whh_e1[r1 * 128 + uslot(s0)], Whh_e1[r1 * 128 + uslot(s0 + 1)]);
        v.z = bfpack(Whh_e1[r0 * 128 + uslot(s2)], Whh_e1[r0 * 128 + uslot(s2 + 1)]);
        v.w = bfpack(Whh_e1[r1 * 128 + uslot(s2)], Whh_e1[r1 * 128 + uslot(s2 + 1)]);
        d_WAb_e1[idx] = v;
    }
    for (int i = tid0; i < 512; i += stride) {
        d_bias_e1[i] = bih_e1[i] + bhh_e1[i];
        d_bias_d1[i] = bih_d1[i] + bhh_d1[i];
    }
    for (int i = tid0; i < 128 * 256; i += stride) {
        int k = i >> 8, g = i & 255;
        d_WihT_e2[i] = Wih_e2[g * 128 + k];
    }
    for (int i = tid0; i < 256; i += stride) d_bias_e2[i] = bih_e2[i] + bhh_e2[i];
}

// ---------------------------------------------------------------------------
// K13: FUSED  e1-encoder (CTAs 1..256, 16 batches each, all-gates-in-thread,
// SMEM-cached fragments, fused pre2 projection, flag release)  +  e2 serial
// scan (CTA 0, consumes pre2 chunks gated by acquire-flags).
// ---------------------------------------------------------------------------
#define FNB 16
#define FXS 18
#define FH2 24
#define FR_U4 (32 * 8 * 32)
#define K13_SMEM (FR_U4 * 16 + 140 * FXS * 4 + 2 * 64 * FH2 * 4)

__global__ __launch_bounds__(256, 1) void k13_fused(const float* __restrict__ x,
                                                    const float* __restrict__ Wih_e1,
                                                    const float* __restrict__ Whh_e2) {
    // ------------------------- CTA 0: e2 serial scan -------------------------
    if (blockIdx.x == 0) {
        if (threadIdx.x >= 128) return;
        __shared__ __align__(16) float k3h[2][64];
        const int tid = threadIdx.x;
        const int w = tid >> 5, l = tid & 31;
        const int j = w * 16 + (l & 15);
        const int q2 = l >> 4;
        const int r0 = q2 ? (64 + j) : j;
        const int r1 = q2 ? (192 + j) : (128 + j);

        u64 w0[32], w1[32];
        const u64* W2 = (const u64*)Whh_e2;
#pragma unroll
        for (int k = 0; k < 32; ++k) { w0[k] = W2[r0 * 32 + k]; w1[k] = W2[r1 * 32 + k]; }

        if (tid < 64) k3h[0][tid] = 0.f;
        float c = 0.f;
        // wait for chunk 0 before first pre2 touch
        while (ld_acq(&d_flags[0]) == 0) {}
        u32 fnext = ld_acq(&d_flags[1]);
        const u64* preb = (const u64*)d_pre2;
        u64 p0 = preb[tid];
        u64 p1 = preb[128 + tid];
        __syncthreads();

        for (int t = 0; t < 4096; ++t) {
            if ((t & 15) == 0) {
                int c2 = (t >> 4) + 1;
                if (c2 < 256) {
                    while (fnext == 0) fnext = ld_acq(&d_flags[c2]);
                    fnext = (c2 + 1 < 256) ? ld_acq(&d_flags[c2 + 1]) : 1u;
                }
            }
            u64 p2 = (t < 4094) ? preb[(t + 2) * 128 + tid] : 0ull;
            const ulonglong2* hp2 = (const ulonglong2*)k3h[t & 1 ? 1 : 0];
            float2 pc = unpk(p0);
            u64 a00 = pack2(pc.x, 0.f), a01 = 0, a02 = 0, a03 = 0;
            u64 a10 = pack2(pc.y, 0.f), a11 = 0, a12 = 0, a13 = 0;
#pragma unroll
            for (int k = 0; k < 16; k += 2) {
                ulonglong2 ha = hp2[k];
                ulonglong2 hb = hp2[k + 1];
                a00 = ffma2u(w0[2 * k],     ha.x, a00);
                a01 = ffma2u(w0[2 * k + 1], ha.y, a01);
                a02 = ffma2u(w0[2 * k + 2], hb.x, a02);
                a03 = ffma2u(w0[2 * k + 3], hb.y, a03);
                a10 = ffma2u(w1[2 * k],     ha.x, a10);
                a11 = ffma2u(w1[2 * k + 1], ha.y, a11);
                a12 = ffma2u(w1[2 * k + 2], hb.x, a12);
                a13 = ffma2u(w1[2 * k + 3], hb.y, a13);
            }
            a00 = add2(add2(a00, a01), add2(a02, a03));
            a10 = add2(add2(a10, a11), add2(a12, a13));
            float2 v0 = unpk(a00), v1 = unpk(a10);
            float s0 = v0.x + v0.y;
            float s1 = v1.x + v1.y;
            float act0 = sigm(s0);
            float act1 = q2 ? sigm(s1) : tanha(s1);
            float o0 = __shfl_xor_sync(0xffffffffu, act0, 16);
            float o1 = __shfl_xor_sync(0xffffffffu, act1, 16);
            float iv = q2 ? o0 : act0;
            float fv = q2 ? act0 : o0;
            float gv = q2 ? o1 : act1;
            float ov = q2 ? act1 : o1;
            c = fmaf(fv, c, iv * gv);
            float h = ov * tanha(c);
            if (q2 == 0) k3h[(t & 1) ^ 1][j] = h;
            __syncthreads();
            p0 = p1; p1 = p2;
        }
        if (tid < 64) d_zvec[tid] = k3h[0][tid];
        return;
    }

    // ------------------------- CTAs 1..256: e1 block -------------------------
    extern __shared__ unsigned char smraw[];
    uint4* frs = (uint4*)smraw;
    float* xs  = (float*)(smraw + FR_U4 * 16);
    u32*   h2A = (u32*)(xs + 140 * FXS);
    u32*   h2B = h2A + 64 * FH2;
    float* hsm = xs;                      // reused after the t-loop ([128][17])

    const int tid = threadIdx.x;
    const int w = tid >> 5, lane = tid & 31;
    const int g = lane >> 2, tg = lane & 3;
    const int cb = blockIdx.x - 1;
    const int base = cb * FNB;

    for (int i = tid; i < FR_U4; i += 256) frs[i] = d_WAb_e1[i];
    for (int i = tid; i < FNB * 140; i += 256) {
        int b = i / 140, t = i - b * 140;
        xs[t * FXS + b] = x[(base + b) * 140 + t];
    }
    for (int i = tid; i < 2 * 64 * FH2; i += 256) h2A[i] = 0u;

    // per-thread constants: 4 gate rows (q*128 + 16w + g), plus row+8
    float wa[4], wbx[4], ba[4], bbx[4];
#pragma unroll
    for (int q = 0; q < 4; ++q) {
        int R = q * 128 + 16 * w + g;
        wa[q] = Wih_e1[R];      wbx[q] = Wih_e1[R + 8];
        ba[q] = d_bias_e1[R];   bbx[q] = d_bias_e1[R + 8];
    }
    const int jb = 16 * w + g;
    float creg[8];
#pragma unroll
    for (int i = 0; i < 8; ++i) creg[i] = 0.f;
    __syncthreads();

    u32* hcur = h2A;
    u32* hnext = h2B;

    for (int t = 0; t < 140; ++t) {
        float Ci[2][4], Cf[2][4], Cg[2][4], Co[2][4];
#pragma unroll
        for (int nt = 0; nt < 2; ++nt) {
            float2 xp = *(const float2*)&xs[t * FXS + nt * 8 + 2 * tg];
            Ci[nt][0] = fmaf(wa[0], xp.x, ba[0]); Ci[nt][1] = fmaf(wa[0], xp.y, ba[0]);
            Ci[nt][2] = fmaf(wbx[0], xp.x, bbx[0]); Ci[nt][3] = fmaf(wbx[0], xp.y, bbx[0]);
            Cf[nt][0] = fmaf(wa[1], xp.x, ba[1]); Cf[nt][1] = fmaf(wa[1], xp.y, ba[1]);
            Cf[nt][2] = fmaf(wbx[1], xp.x, bbx[1]); Cf[nt][3] = fmaf(wbx[1], xp.y, bbx[1]);
            Cg[nt][0] = fmaf(wa[2], xp.x, ba[2]); Cg[nt][1] = fmaf(wa[2], xp.y, ba[2]);
            Cg[nt][2] = fmaf(wbx[2], xp.x, bbx[2]); Cg[nt][3] = fmaf(wbx[2], xp.y, bbx[2]);
            Co[nt][0] = fmaf(wa[3], xp.x, ba[3]); Co[nt][1] = fmaf(wa[3], xp.y, ba[3]);
            Co[nt][2] = fmaf(wbx[3], xp.x, bbx[3]); Co[nt][3] = fmaf(wbx[3], xp.y, bbx[3]);
        }
#pragma unroll
        for (int kt = 0; kt < 8; ++kt) {
            uint4 fI = frs[(w * 8 + kt) * 32 + lane];
            uint4 fF = frs[((w + 8) * 8 + kt) * 32 + lane];
            uint4 fG = frs[((w + 16) * 8 + kt) * 32 + lane];
            uint4 fO = frs[((w + 24) * 8 + kt) * 32 + lane];
#pragma unroll
            for (int nt = 0; nt < 2; ++nt) {
                u32 b0 = hcur[(8 * kt + tg) * FH2 + nt * 8 + g];
                u32 b1 = hcur[(8 * kt + 4 + tg) * FH2 + nt * 8 + g];
                mma16816(Ci[nt][0], Ci[nt][1], Ci[nt][2], Ci[nt][3],
                         fI.x, fI.y, fI.z, fI.w, b0, b1);
                mma16816(Cf[nt][0], Cf[nt][1], Cf[nt][2], Cf[nt][3],
                         fF.x, fF.y, fF.z, fF.w, b0, b1);
                mma16816(Cg[nt][0], Cg[nt][1], Cg[nt][2], Cg[nt][3],
                         fG.x, fG.y, fG.z, fG.w, b0, b1);
                mma16816(Co[nt][0], Co[nt][1], Co[nt][2], Co[nt][3],
                         fO.x, fO.y, fO.z, fO.w, b0, b1);
            }
        }
        // in-thread LSTM update (all 4 gates local) + h2 pack store
#pragma unroll
        for (int nt = 0; nt < 2; ++nt) {
            int bc = nt * 8 + 2 * tg;
            float hp[4];
#pragma unroll
            for (int p = 0; p < 4; ++p) {
                float iv = sigm(Ci[nt][p]);
                float fv = sigm(Cf[nt][p]);
                float gv = tanha(Cg[nt][p]);
                float ov = sigm(Co[nt][p]);
                int ci = nt * 4 + p;
                creg[ci] = fmaf(fv, creg[ci], iv * gv);
                hp[p] = ov * tanha(creg[ci]);
            }
            if (t < 139) {
                hnext[(8 * w + g) * FH2 + bc]     = bfpack(hp[0], hp[2]);
                hnext[(8 * w + g) * FH2 + bc + 1] = bfpack(hp[1], hp[3]);
            } else {
                hsm[jb * 17 + bc]           = hp[0];
                hsm[jb * 17 + bc + 1]       = hp[1];
                hsm[(jb + 8) * 17 + bc]     = hp[2];
                hsm[(jb + 8) * 17 + bc + 1] = hp[3];
            }
        }
        __syncthreads();
        u32* tmp = hcur; hcur = hnext; hnext = tmp;
    }

    // fused pre2 projection: row = tid, 16 batches
    {
        const int gg = tid;
        float acc[16];
#pragma unroll
        for (int b = 0; b < 16; ++b) acc[b] = 0.f;
        for (int k = 0; k < 128; ++k) {
            float wv = d_WihT_e2[k * 256 + gg];
            const float* hr = hsm + k * 17;
#pragma unroll
            for (int b = 0; b < 16; ++b) acc[b] = fmaf(hr[b], wv, acc[b]);
        }
        float bv = d_bias_e2[gg];
        int q = gg >> 6, j = gg & 63;
        int q2v = q & 1, slot = q >> 1;
        int tid2 = (j >> 4) * 32 + (q2v << 4) + (j & 15);
        int dst = tid2 * 2 + slot;
#pragma unroll
        for (int b = 0; b < 16; ++b)
            d_pre2[(base + b) * 256 + dst] = acc[b] + bv;
    }
    __threadfence();
    __syncthreads();
    if (tid == 0) st_rel(&d_flags[cb], 1u);
}

// ---------------------------------------------------------------------------
// K4: decoder d1 split across 2-CTA cluster, weights in regs; fused d2.
// (R16-identical, passing version)
// ---------------------------------------------------------------------------
__global__ __launch_bounds__(512, 1) __cluster_dims__(2, 1, 1)
void k4_dec(const float* __restrict__ Wih_d1,
            const float* __restrict__ Whh_d1,
            const float* __restrict__ Wih_d2,
            const float* __restrict__ Whh_d2,
            const float* __restrict__ bih_d2,
            const float* __restrict__ bhh_d2,
            float* __restrict__ out) {
    __shared__ __align__(16) float hbuf[2][128];
    __shared__ __align__(8) u64 mbar[1];
    __shared__ float zsh[64];

    const int tid = threadIdx.x;
    u32 rank;
    asm("mov.u32 %0, %%cluster_ctarank;" : "=r"(rank));
    const u32 peer = rank ^ 1u;

    const u32 mbar_a = smem_u32(mbar);
    const u32 hbuf_a = smem_u32(&hbuf[0][0]);

    if (tid == 0) {
        asm volatile("mbarrier.init.shared.b64 [%0], %1;" :: "r"(mbar_a), "r"(32u) : "memory");
    }
    if (tid < 64) zsh[tid] = d_zvec[tid];
    if (tid < 128) hbuf[0][tid] = 0.f;
    __syncthreads();
    asm volatile("barrier.cluster.arrive.aligned;" ::: "memory");
    asm volatile("barrier.cluster.wait.aligned;" ::: "memory");

    const int kh = tid & 1;
    const int q  = (tid >> 1) & 3;
    const int jj = tid >> 3;
    const int J  = 64 * (int)rank + jj;
    const int row = q * 128 + J;

    float4 Wreg[16];
    {
        const float4* wp = (const float4*)(Whh_d1 + (size_t)row * 128 + kh * 64);
#pragma unroll
        for (int i = 0; i < 16; ++i) Wreg[i] = wp[i];
    }
    float wz = (kh == 0) ? d_bias_d1[row] : 0.f;
#pragma unroll 8
    for (int k = 0; k < 32; ++k)
        wz = fmaf(Wih_d1[row * 64 + kh * 32 + k], zsh[kh * 32 + k], wz);

    float wd2[16], b2[4], wh[4];
    float c2s = 0.f, h2s = 0.f;
    if (rank == 0 && tid < 32) {
#pragma unroll
        for (int qq = 0; qq < 4; ++qq) {
#pragma unroll
            for (int m = 0; m < 4; ++m) wd2[qq * 4 + m] = Wih_d2[qq * 128 + m * 32 + tid];
            b2[qq] = bih_d2[qq] + bhh_d2[qq];
            wh[qq] = Whh_d2[qq];
        }
    }

    float c = 0.f;
    u32 ph = 0;

    for (int t = 0; t < 140; ++t) {
        const int rb = t & 1;
        const int wb = rb ^ 1;
        const ulonglong2* hp = (const ulonglong2*)(hbuf[rb]) + 16 * kh;
        u64 a0 = pack2(wz, 0.f), a1 = 0, a2 = 0, a3 = 0;
#pragma unroll
        for (int i = 0; i < 4; ++i) {
            ulonglong2 hA = hp[4 * i],     hB = hp[4 * i + 1];
            ulonglong2 hC = hp[4 * i + 2], hD = hp[4 * i + 3];
            a0 = ffma2u(pack2(Wreg[4 * i].x,     Wreg[4 * i].y),     hA.x, a0);
            a1 = ffma2u(pack2(Wreg[4 * i].z,     Wreg[4 * i].w),     hA.y, a1);
            a2 = ffma2u(pack2(Wreg[4 * i + 1].x, Wreg[4 * i + 1].y), hB.x, a2);
            a3 = ffma2u(pack2(Wreg[4 * i + 1].z, Wreg[4 * i + 1].w), hB.y, a3);
            a0 = ffma2u(pack2(Wreg[4 * i + 2].x, Wreg[4 * i + 2].y), hC.x, a0);
            a1 = ffma2u(pack2(Wreg[4 * i + 2].z, Wreg[4 * i + 2].w), hC.y, a1);
            a2 = ffma2u(pack2(Wreg[4 * i + 3].x, Wreg[4 * i + 3].y), hD.x, a2);
            a3 = ffma2u(pack2(Wreg[4 * i + 3].z, Wreg[4 * i + 3].w), hD.y, a3);
        }
        a0 = add2(add2(a0, a1), add2(a2, a3));
        float2 v = unpk(a0);
        float s = v.x + v.y;
        s += __shfl_xor_sync(0xffffffffu, s, 1);
        float act = (q == 2) ? tanha(s) : sigm(s);
        float r4 = __shfl_xor_sync(0xffffffffu, act, 4);
        float ig = act * r4;
        float r2 = __shfl_xor_sync(0xffffffffu, ig, 2);
        float hval = 0.f;
        if (q == 1) {
            c = fmaf(act, c, r2);
            hval = r4 * tanha(c);
            if (kh == 0) hbuf[wb][J] = hval;
        }
        __syncthreads();
        if (tid >= 32 && tid < 64) {
            int i = tid - 32;
            int idx = 32 * (int)rank + i;
            u64 val = ((const u64*)hbuf[wb])[idx];
            u32 dsta = mapa_peer(hbuf_a + (u32)(wb * 128 + 0) * 4 + (u32)idx * 8, peer);
            asm volatile("st.shared::cluster.b64 [%0], %1;" :: "r"(dsta), "l"(val) : "memory");
            u32 pb = mapa_peer(mbar_a, peer);
            asm volatile("mbarrier.arrive.release.cluster.shared::cluster.b64 _, [%0];"
                         :: "r"(pb) : "memory");
        }
        mbar_wait_parity_cluster(mbar_a, ph);
        ph ^= 1u;
        if (rank == 0 && tid < 32) {
            float p0 = 0.f, p1 = 0.f, p2 = 0.f, p3 = 0.f;
#pragma unroll
            for (int m = 0; m < 4; ++m) {
                float hv = hbuf[wb][m * 32 + tid];
                p0 = fmaf(wd2[0 * 4 + m], hv, p0);
                p1 = fmaf(wd2[1 * 4 + m], hv, p1);
                p2 = fmaf(wd2[2 * 4 + m], hv, p2);
                p3 = fmaf(wd2[3 * 4 + m], hv, p3);
            }
#pragma unroll
            for (int off = 16; off > 0; off >>= 1) {
                p0 += __shfl_xor_sync(0xffffffffu, p0, off);
                p1 += __shfl_xor_sync(0xffffffffu, p1, off);
                p2 += __shfl_xor_sync(0xffffffffu, p2, off);
                p3 += __shfl_xor_sync(0xffffffffu, p3, off);
            }
            float iv2 = sigm(p0 + b2[0] + wh[0] * h2s);
            float fv2 = sigm(p1 + b2[1] + wh[1] * h2s);
            float gv2 = tanha(p2 + b2[2] + wh[2] * h2s);
            float ov2 = sigm(p3 + b2[3] + wh[3] * h2s);
            c2s = fmaf(fv2, c2s, iv2 * gv2);
            h2s = ov2 * tanha(c2s);
            if (tid == 0) out[t] = h2s;
        }
    }
    asm volatile("barrier.cluster.arrive.aligned;" ::: "memory");
    asm volatile("barrier.cluster.wait.aligned;" ::: "memory");
}

// ---------------------------------------------------------------------------
// Launch
// ---------------------------------------------------------------------------
extern "C" void kernel_launch(void* const* d_in, const int* in_sizes, int n_in,
                              void* d_out, int out_size) {
    const float* x      = (const float*)d_in[0];
    const float* Wih_e1 = (const float*)d_in[1];
    const float* Whh_e1 = (const float*)d_in[2];
    const float* bih_e1 = (const float*)d_in[3];
    const float* bhh_e1 = (const float*)d_in[4];
    const float* Wih_e2 = (const float*)d_in[5];
    const float* Whh_e2 = (const float*)d_in[6];
    const float* bih_e2 = (const float*)d_in[7];
    const float* bhh_e2 = (const float*)d_in[8];
    const float* Wih_d1 = (const float*)d_in[9];
    const float* Whh_d1 = (const float*)d_in[10];
    const float* bih_d1 = (const float*)d_in[11];
    const float* bhh_d1 = (const float*)d_in[12];
    const float* Wih_d2 = (const float*)d_in[13];
    const float* Whh_d2 = (const float*)d_in[14];
    const float* bih_d2 = (const float*)d_in[15];
    const float* bhh_d2 = (const float*)d_in[16];
    float* out = (float*)d_out;
    (void)in_sizes; (void)n_in; (void)out_size;

    cudaFuncSetAttribute(k13_fused, cudaFuncAttributeMaxDynamicSharedMemorySize, K13_SMEM);

    k0_prep<<<64, 256>>>(Whh_e1, bih_e1, bhh_e1, Wih_e2, bih_e2, bhh_e2,
                         bih_d1, bhh_d1);
    k13_fused<<<257, 256, K13_SMEM>>>(x, Wih_e1, Whh_e2);
    k4_dec<<<2, 512>>>(Wih_d1, Whh_d1, Wih_d2, Whh_d2, bih_d2, bhh_d2, out);
}